// round 17
// baseline (speedup 1.0000x reference)
#include <cuda_runtime.h>
#include <cuda_fp16.h>
#include <cstdint>

// AdderNet: out[n,h,w,f] = sum_{dh,dw,c} |Xpad[n,h+dh-1,w+dw-1,c] - F[f,dh,dw,c]|
// X [8,32,32,32] f32 NHWC, F [64,3,3,32] f32, out [8,32,32,64] f32.
//
// R17: two-kernel. k1 pre-converts X -> fp16 padded+swizzled global
// [n][rowp 34][c8 4][s 36] and F -> fp16 padded [f][j 37]. k2's prologue is
// just 2x cp.async.bulk (contiguous 6912B + 9472B) + mbarrier wait — no cvt,
// no bounds, no index math, half the bytes. Mainloop identical to R16
// (16 flat fp16 chains, folded abs, per-dh fp32 flush, rel_err ~1.4e-4).
// Tile 4px x 1f, block 128 = wq(8) x fg(16), grid (256 nh, 4 fq).

#define XS_CH (3 * 4 * 36)          // 432 chunks (16B = 8 ch fp16)
#define FSTRIDE 37
#define FS_CH (16 * FSTRIDE)        // 592 chunks
#define SMEM_BYTES ((XS_CH + FS_CH) * 16 + 16)   // + mbarrier

#define XP_CHUNKS (8 * 34 * 4 * 36)              // 39168
#define FH_CHUNKS (64 * FSTRIDE)                 // 2368

__device__ __align__(16) uint4 g_Xp[XP_CHUNKS];  // [n][rp][c8][s], rp=row+1
__device__ __align__(16) uint4 g_Fh[FH_CHUNKS];  // [f][j], j=36 zero pad

struct __align__(16) H2x4 { __half2 a, b, c, d; };

__device__ __forceinline__ H2x4 cvt_chunk(float4 lo, float4 hi) {
    H2x4 r;
    r.a = __float22half2_rn(make_float2(lo.x, lo.y));
    r.b = __float22half2_rn(make_float2(lo.z, lo.w));
    r.c = __float22half2_rn(make_float2(hi.x, hi.y));
    r.d = __float22half2_rn(make_float2(hi.z, hi.w));
    return r;
}

// ---------------- k1: pre-convert X and F to fp16 layouts ----------------
__global__ void preconvert_kernel(const float* __restrict__ X,
                                  const float* __restrict__ Fw) {
    const int i = blockIdx.x * 256 + threadIdx.x;
    const float4* Xg4 = reinterpret_cast<const float4*>(X);
    const float4* Fg4 = reinterpret_cast<const float4*>(Fw);
    const __half2 hz = __float2half2_rn(0.f);

    if (i < XP_CHUNKS) {
        int s = i % 36;
        int t = i / 36;
        int c8 = t & 3;
        t >>= 2;
        int rp = t % 34;
        int n = t / 34;
        int q = s % 9, r = s / 9;
        int w = 4 * q + r - 1;
        int row = rp - 1;
        H2x4 v;
        if (row >= 0 && row < 32 && w >= 0 && w < 32) {
            int g = (((n * 32) + row) * 32 + w) * 8 + c8 * 2;
            v = cvt_chunk(Xg4[g], Xg4[g + 1]);
        } else {
            v.a = hz; v.b = hz; v.c = hz; v.d = hz;
        }
        g_Xp[i] = *reinterpret_cast<uint4*>(&v);
    } else if (i < XP_CHUNKS + FH_CHUNKS) {
        int k = i - XP_CHUNKS;
        int f = k / FSTRIDE;
        int j = k - f * FSTRIDE;
        H2x4 v;
        if (j < 36) {
            v = cvt_chunk(Fg4[f * 72 + j * 2], Fg4[f * 72 + j * 2 + 1]);
        } else {
            v.a = hz; v.b = hz; v.c = hz; v.d = hz;
        }
        g_Fh[k] = *reinterpret_cast<uint4*>(&v);
    }
}

// ---------------- k2: main kernel ----------------

#define PXUPD(p, xa, xb, xc)                                              \
    cA##p = __hadd2(cA##p, __habs2(__hsub2((xa).a, f0.a)));               \
    cB##p = __hadd2(cB##p, __habs2(__hsub2((xa).b, f0.b)));               \
    cC##p = __hadd2(cC##p, __habs2(__hsub2((xa).c, f0.c)));               \
    cD##p = __hadd2(cD##p, __habs2(__hsub2((xa).d, f0.d)));               \
    cA##p = __hadd2(cA##p, __habs2(__hsub2((xb).a, f1.a)));               \
    cB##p = __hadd2(cB##p, __habs2(__hsub2((xb).b, f1.b)));               \
    cC##p = __hadd2(cC##p, __habs2(__hsub2((xb).c, f1.c)));               \
    cD##p = __hadd2(cD##p, __habs2(__hsub2((xb).d, f1.d)));               \
    cA##p = __hadd2(cA##p, __habs2(__hsub2((xc).a, f2.a)));               \
    cB##p = __hadd2(cB##p, __habs2(__hsub2((xc).b, f2.b)));               \
    cC##p = __hadd2(cC##p, __habs2(__hsub2((xc).c, f2.c)));               \
    cD##p = __hadd2(cD##p, __habs2(__hsub2((xc).d, f2.d)))

#define FLUSH(p)                                                          \
    {                                                                     \
        __half2 m = __hadd2(__hadd2(cA##p, cB##p), __hadd2(cC##p, cD##p));\
        float2 t = __half22float2(m);                                     \
        acc##p.x += t.x; acc##p.y += t.y;                                 \
        cA##p = hz; cB##p = hz; cC##p = hz; cD##p = hz;                   \
    }

__global__ __launch_bounds__(128, 8)
void adder_layer_kernel(float* __restrict__ out) {
    extern __shared__ __align__(16) H2x4 smem[];
    H2x4* Xs = smem;                  // [(dh*4 + c8)*36 + s]
    H2x4* Fs = smem + XS_CH;          // [fl*37 + (dh*3+dw)*4 + c8]

    const int tid = threadIdx.x;
    const int nh = blockIdx.x;        // n*32 + h
    const int fbase = blockIdx.y * 16;
    const int n = nh >> 5;
    const int h = nh & 31;

    // smem u32 addresses
    uint32_t smem_u32;
    asm("{ .reg .u64 t; cvta.to.shared.u64 t, %1; cvt.u32.u64 %0, t; }"
        : "=r"(smem_u32) : "l"(smem));
    const uint32_t mbar = smem_u32 + (XS_CH + FS_CH) * 16;

    if (tid == 0) {
        asm volatile("mbarrier.init.shared.b64 [%0], %1;"
                     :: "r"(mbar), "r"(1u) : "memory");
    }
    __syncthreads();

    if (tid == 0) {
        const uint32_t total = 3 * 4 * 36 * 16 + 16 * FSTRIDE * 16;  // 6912+9472
        asm volatile("mbarrier.arrive.expect_tx.shared.b64 _, [%0], %1;"
                     :: "r"(mbar), "r"(total) : "memory");
        const uint4* xsrc = g_Xp + ((n * 34 + h) * 4) * 36;
        const uint4* fsrc = g_Fh + fbase * FSTRIDE;
        asm volatile(
            "cp.async.bulk.shared::cta.global.mbarrier::complete_tx::bytes "
            "[%0], [%1], %2, [%3];"
            :: "r"(smem_u32), "l"(xsrc), "r"(3 * 4 * 36 * 16), "r"(mbar)
            : "memory");
        asm volatile(
            "cp.async.bulk.shared::cta.global.mbarrier::complete_tx::bytes "
            "[%0], [%1], %2, [%3];"
            :: "r"(smem_u32 + XS_CH * 16), "l"(fsrc), "r"(16 * FSTRIDE * 16),
               "r"(mbar)
            : "memory");
    }

    // wait (parity 0, acquire)
    {
        uint32_t done;
        asm volatile(
            "{\n\t.reg .pred p;\n\t"
            "mbarrier.try_wait.parity.acquire.cta.shared::cta.b64 p, [%1], 0;\n\t"
            "selp.b32 %0, 1, 0, p;\n\t}"
            : "=r"(done) : "r"(mbar) : "memory");
        if (!done) {
            asm volatile(
                "{\n\t.reg .pred P1;\n\t"
                "WAIT_LOOP:\n\t"
                "mbarrier.try_wait.parity.acquire.cta.shared::cta.b64 P1, [%0], 0, 0x989680;\n\t"
                "@P1 bra.uni WAIT_DONE;\n\t"
                "bra.uni WAIT_LOOP;\n\t"
                "WAIT_DONE:\n\t}"
                :: "r"(mbar) : "memory");
        }
    }

    const int wq = tid & 7;           // pixels w = 4wq .. 4wq+3
    const int fg = tid >> 3;          // 0..15 -> filter fbase + fg

    const __half2 hz = __float2half2_rn(0.f);
    float2 acc0 = make_float2(0.f, 0.f), acc1 = make_float2(0.f, 0.f);
    float2 acc2 = make_float2(0.f, 0.f), acc3 = make_float2(0.f, 0.f);

    __half2 cA0 = hz, cB0 = hz, cC0 = hz, cD0 = hz;
    __half2 cA1 = hz, cB1 = hz, cC1 = hz, cD1 = hz;
    __half2 cA2 = hz, cB2 = hz, cC2 = hz, cD2 = hz;
    __half2 cA3 = hz, cB3 = hz, cC3 = hz, cD3 = hz;

    const H2x4* Fb = Fs + fg * FSTRIDE;

    #pragma unroll
    for (int dh = 0; dh < 3; dh++) {
        #pragma unroll
        for (int c8 = 0; c8 < 4; c8++) {
            const int kk = dh * 4 + c8;
            const int j0 = dh * 12 + c8;

            const H2x4* xr = Xs + kk * 36 + wq;
            H2x4 x0 = xr[0];
            H2x4 x1 = xr[9];
            H2x4 x2 = xr[18];
            H2x4 x3 = xr[27];
            H2x4 x4 = xr[1];
            H2x4 x5 = xr[10];

            H2x4 f0 = Fb[j0], f1 = Fb[j0 + 4], f2 = Fb[j0 + 8];

            PXUPD(0, x0, x1, x2);
            PXUPD(1, x1, x2, x3);
            PXUPD(2, x2, x3, x4);
            PXUPD(3, x3, x4, x5);
        }
        FLUSH(0); FLUSH(1); FLUSH(2); FLUSH(3);
    }

    float* obase = out + ((nh * 32) + 4 * wq) * 64 + fbase + fg;
    obase[0]   = acc0.x + acc0.y;
    obase[64]  = acc1.x + acc1.y;
    obase[128] = acc2.x + acc2.y;
    obase[192] = acc3.x + acc3.y;
}

extern "C" void kernel_launch(void* const* d_in, const int* in_sizes, int n_in,
                              void* d_out, int out_size) {
    const float* X = (const float*)d_in[0];
    const float* Fw = (const float*)d_in[1];
    float* out = (float*)d_out;

    // k1: pre-convert (writes g_Xp, g_Fh)
    const int total = XP_CHUNKS + FH_CHUNKS;
    preconvert_kernel<<<(total + 255) / 256, 256>>>(X, Fw);

    // k2: main
    cudaFuncSetAttribute(adder_layer_kernel,
                         cudaFuncAttributeMaxDynamicSharedMemorySize, SMEM_BYTES);
    dim3 grid(256, 4);
    adder_layer_kernel<<<grid, 128, SMEM_BYTES>>>(out);
}